// round 7
// baseline (speedup 1.0000x reference)
#include <cuda_runtime.h>
#include <cstdint>
#include <math.h>

// Problem constants
#define MROWS 10000
#define HID   64
#define KSPL  5          // K-split for the big GEMM (10000/5 = 2000 = 125 * BK)

// GEMM tiling: CTA tile 128x64, 2 warps, warp tile 64x64 (A-replication 1, B-replication 2)
#define BM 128
#define BN 64
#define BK 16
#define KPAD 20          // A smem row stride (floats): conflict-free a-frag reads
#define NPAD 72          // B smem row stride (floats): conflict-free b-frag reads
#define NTHREADS 64

#define STAGES 5
#define WAIT_N 3         // STAGES-2: oldest outstanding group complete
#define AS_SZ (BM * KPAD)        // 2560 floats
#define BS_SZ (BK * NPAD)        // 1152 floats
#define STAGE_FLTS (AS_SZ + BS_SZ)               // 3712
#define SMEM_BYTES (STAGES * STAGE_FLTS * 4)     // 74240 (x3 CTAs = 222.7KB/SM)

// Scratch (static device globals: no allocation anywhere)
__device__ __align__(16) float g_xw[2 * MROWS * HID];          // x@W1, x@W2
__device__ __align__(16) float g_part[2 * KSPL * MROWS * HID]; // K-split partials
__device__ __align__(16) float g_emb[MROWS * HID];             // fallback emb target

__device__ __forceinline__ uint32_t f2tf(float x) {
    uint32_t u;
    asm("cvt.rna.tf32.f32 %0, %1;" : "=r"(u) : "f"(x));
    return u;
}

__device__ __forceinline__ void cp16(uint32_t dst, const void* src, bool v) {
    const int sz = v ? 16 : 0;   // src-size 0 => zero-fill, no gmem access
    asm volatile("cp.async.cg.shared.global [%0], [%1], 16, %2;\n"
                 :: "r"(dst), "l"(src), "r"(sz));
}

__device__ __forceinline__ void cp_commit() {
    asm volatile("cp.async.commit_group;\n");
}

__device__ __forceinline__ void cp_wait() {
    asm volatile("cp.async.wait_group %0;\n" :: "n"(WAIT_N));
}

__device__ __forceinline__ void mma8(float& c0, float& c1, float& c2, float& c3,
                                     uint32_t a0, uint32_t a1, uint32_t a2, uint32_t a3,
                                     uint32_t b0, uint32_t b1) {
    asm("mma.sync.aligned.m16n8k8.row.col.f32.tf32.tf32.f32 "
        "{%0,%1,%2,%3}, {%4,%5,%6,%7}, {%8,%9}, {%0,%1,%2,%3};"
        : "+f"(c0), "+f"(c1), "+f"(c2), "+f"(c3)
        : "r"(a0), "r"(a1), "r"(a2), "r"(a3), "r"(b0), "r"(b1));
}

// C[(by*gridDim.z + bz)*M*64 + m*64 + n] = A_by[m, kBase:kBase+kChunk] @ B_by[kBase:..., :64]
// A row-major (row stride lda), B row-major [K,64]. kChunk % BK == 0 guaranteed.
// 64 threads = 2 warps, each computes a 64x64 output tile. 5-stage cp.async pipeline.
__global__ __launch_bounds__(NTHREADS, 3)
void gemm_tf32_kernel(const float* __restrict__ A0, const float* __restrict__ A1,
                      const float* __restrict__ B0, const float* __restrict__ B1,
                      float* __restrict__ Cbase, int M, int lda, int kChunk)
{
    extern __shared__ __align__(16) float dsmem[];

    const int tid  = threadIdx.x;
    const float* A = blockIdx.y ? A1 : A0;
    const float* B = blockIdx.y ? B1 : B0;
    float* C = Cbase + (size_t)(blockIdx.y * gridDim.z + blockIdx.z) * ((size_t)M * BN);

    const int m0     = blockIdx.x * BM;
    const int kBase  = blockIdx.z * kChunk;
    const int ktiles = kChunk / BK;

    const int lane = tid & 31;
    const int warp = tid >> 5;          // 0..1
    const int wm0  = warp * 64;         // warp tile 64(m) x 64(n)
    const int r    = lane >> 2;         // 0..7
    const int c    = lane & 3;          // 0..3

    // ---- staging maps (64 threads) ----
    // A: 512 chunks of 16B per stage; thread handles rows (tid>>2)+16i, col chunk (tid&3)*4
    const int aRowBase = tid >> 2;          // 0..15
    const int aCol     = (tid & 3) * 4;     // 0,4,8,12
    // B: 256 chunks; thread handles rows (tid>>4)+4j, col chunk (tid&15)*4
    const int bRowBase = tid >> 4;          // 0..3
    const int bCol     = (tid & 15) * 4;    // 0..60

    const float* gA[8];
    bool         va[8];
#pragma unroll
    for (int i = 0; i < 8; ++i) {
        const int row = aRowBase + 16 * i;       // 0..127
        const int gr  = m0 + row;
        va[i] = gr < M;
        gA[i] = A + (size_t)(va[i] ? gr : 0) * lda + kBase + aCol;
    }
    const float* gBp[4];
#pragma unroll
    for (int j = 0; j < 4; ++j)
        gBp[j] = B + (size_t)(kBase + bRowBase + 4 * j) * BN + bCol;

    const uint32_t sBase = (uint32_t)__cvta_generic_to_shared(dsmem);
    uint32_t dA[8], dB[4];
#pragma unroll
    for (int i = 0; i < 8; ++i)
        dA[i] = sBase + ((aRowBase + 16 * i) * KPAD + aCol) * 4;
#pragma unroll
    for (int j = 0; j < 4; ++j)
        dB[j] = sBase + (AS_SZ + (bRowBase + 4 * j) * NPAD + bCol) * 4;
    const uint32_t stgB = STAGE_FLTS * 4;

    float acc[4][8][4];
#pragma unroll
    for (int a = 0; a < 4; ++a)
#pragma unroll
        for (int b = 0; b < 8; ++b)
#pragma unroll
            for (int d = 0; d < 4; ++d) acc[a][b][d] = 0.f;

    // prologue: fill STAGES-1 stages
#pragma unroll
    for (int s = 0; s < STAGES - 1; ++s) {
        if (s < ktiles) {
            const uint32_t so = s * stgB;
#pragma unroll
            for (int i = 0; i < 8; ++i) cp16(dA[i] + so, gA[i] + s * BK, va[i]);
#pragma unroll
            for (int j = 0; j < 4; ++j) cp16(dB[j] + so, gBp[j] + (size_t)s * BK * BN, true);
        }
        cp_commit();
    }

    int rd = 0;                 // stage holding tile t
    int wr = STAGES - 1;        // stage for tile t+STAGES-1

    for (int t = 0; t < ktiles; ++t) {
        cp_wait();              // tile t resident
        __syncthreads();        // all threads past iteration t-1's compute

        {   // issue loads for tile t+STAGES-1 into stage wr
            const int tt = t + STAGES - 1;
            if (tt < ktiles) {
                const uint32_t so = wr * stgB;
#pragma unroll
                for (int i = 0; i < 8; ++i) cp16(dA[i] + so, gA[i] + tt * BK, va[i]);
#pragma unroll
                for (int j = 0; j < 4; ++j) cp16(dB[j] + so, gBp[j] + (size_t)tt * BK * BN, true);
            }
            cp_commit();
            if (++wr == STAGES) wr = 0;
        }

        const float* Ab = dsmem + rd * STAGE_FLTS;
        const float* Bb = Ab + AS_SZ;
        if (++rd == STAGES) rd = 0;

#pragma unroll
        for (int ks = 0; ks < 2; ++ks) {
            const int k8 = ks * 8;
            uint32_t af[4][4], bf[8][2];
#pragma unroll
            for (int mt = 0; mt < 4; ++mt) {
                const int row = wm0 + mt * 16 + r;
                af[mt][0] = f2tf(Ab[row       * KPAD + k8 + c]);
                af[mt][1] = f2tf(Ab[(row + 8) * KPAD + k8 + c]);
                af[mt][2] = f2tf(Ab[row       * KPAD + k8 + c + 4]);
                af[mt][3] = f2tf(Ab[(row + 8) * KPAD + k8 + c + 4]);
            }
#pragma unroll
            for (int nt = 0; nt < 8; ++nt) {
                const int col = nt * 8 + r;
                bf[nt][0] = f2tf(Bb[(k8 + c)     * NPAD + col]);
                bf[nt][1] = f2tf(Bb[(k8 + c + 4) * NPAD + col]);
            }
#pragma unroll
            for (int mt = 0; mt < 4; ++mt)
#pragma unroll
                for (int nt = 0; nt < 8; ++nt)
                    mma8(acc[mt][nt][0], acc[mt][nt][1], acc[mt][nt][2], acc[mt][nt][3],
                         af[mt][0], af[mt][1], af[mt][2], af[mt][3],
                         bf[nt][0], bf[nt][1]);
        }
    }

    // epilogue: c0,c1 -> (row=r, cols 2c,2c+1); c2,c3 -> (row=r+8)
#pragma unroll
    for (int mt = 0; mt < 4; ++mt) {
        const int rowA = m0 + wm0 + mt * 16 + r;
        const int rowB = rowA + 8;
#pragma unroll
        for (int nt = 0; nt < 8; ++nt) {
            const int col = nt * 8 + 2 * c;
            if (rowA < M)
                *(float2*)(C + (size_t)rowA * BN + col) =
                    make_float2(acc[mt][nt][0], acc[mt][nt][1]);
            if (rowB < M)
                *(float2*)(C + (size_t)rowB * BN + col) =
                    make_float2(acc[mt][nt][2], acc[mt][nt][3]);
        }
    }
}

// One warp per node row: reduce K-split partials + bias, 2-view attention
// softmax fuse, DEC soft assignment q.
__global__ void fuse_kernel(const float* __restrict__ part,
                            const float* __restrict__ b1, const float* __restrict__ b2,
                            const float* __restrict__ attnw, const float* __restrict__ clus,
                            float* __restrict__ emb_out, float* __restrict__ q_out, int M)
{
    const int warp = threadIdx.x >> 5;
    const int lane = threadIdx.x & 31;
    const int i = blockIdx.x * 8 + warp;
    if (i >= M) return;

    const int h0 = lane, h1 = lane + 32;
    const size_t M64 = (size_t)M * HID;

    float e1a = b1[h0], e1b = b1[h1];
    float e2a = b2[h0], e2b = b2[h1];
    const float* p1 = part + (size_t)i * HID;
    const float* p2 = part + (size_t)KSPL * M64 + (size_t)i * HID;
#pragma unroll
    for (int z = 0; z < KSPL; ++z) {
        e1a += p1[(size_t)z * M64 + h0];
        e1b += p1[(size_t)z * M64 + h1];
        e2a += p2[(size_t)z * M64 + h0];
        e2b += p2[(size_t)z * M64 + h1];
    }

    const float aw0 = attnw[h0], aw1 = attnw[h1];
    float w1 = e1a * aw0 + e1b * aw1;
    float w2 = e2a * aw0 + e2b * aw1;
#pragma unroll
    for (int o = 16; o; o >>= 1) {
        w1 += __shfl_xor_sync(0xffffffffu, w1, o);
        w2 += __shfl_xor_sync(0xffffffffu, w2, o);
    }
    const float mx  = fmaxf(w1, w2);
    const float x1  = expf(w1 - mx);
    const float x2  = expf(w2 - mx);
    const float inv = 1.f / (x1 + x2);
    const float be1 = x1 * inv, be2 = x2 * inv;

    const float ea = be1 * e1a + be2 * e2a;
    const float eb = be1 * e1b + be2 * e2b;
    emb_out[(size_t)i * HID + h0] = ea;
    emb_out[(size_t)i * HID + h1] = eb;

    if (!q_out) return;

    float tq[10];
    float s = 0.f;
#pragma unroll
    for (int k = 0; k < 10; ++k) {
        const float da = ea - clus[k * HID + h0];
        const float db = eb - clus[k * HID + h1];
        float d2 = da * da + db * db;
#pragma unroll
        for (int o = 16; o; o >>= 1) d2 += __shfl_xor_sync(0xffffffffu, d2, o);
        // q = (1/(1+d2/0.2))^0.6 ^1.2 (/2 cancels under row normalization)
        float tk = 1.f / (1.f + d2 * 5.0f);
        tk = powf(tk, 0.72f);
        tq[k] = tk;
        s += tk;
    }
    if (lane < 10) q_out[(size_t)i * 10 + lane] = tq[lane] / s;
}

extern "C" void kernel_launch(void* const* d_in, const int* in_sizes, int n_in,
                              void* d_out, int out_size)
{
    const float* x    = (const float*)d_in[0];
    const float* adj1 = (const float*)d_in[1];
    const float* adj2 = (const float*)d_in[2];
    const float* W1   = (const float*)d_in[3];
    const float* b1   = (const float*)d_in[4];
    const float* W2   = (const float*)d_in[5];
    const float* b2   = (const float*)d_in[6];
    const float* attn = (const float*)d_in[7];
    const float* clus = (const float*)d_in[8];

    float *xw, *part, *embS;
    cudaGetSymbolAddress((void**)&xw,   g_xw);
    cudaGetSymbolAddress((void**)&part, g_part);
    cudaGetSymbolAddress((void**)&embS, g_emb);

    cudaFuncSetAttribute(gemm_tf32_kernel,
                         cudaFuncAttributeMaxDynamicSharedMemorySize, SMEM_BYTES);

    const int mtiles = (MROWS + BM - 1) / BM;   // 79

    // GEMM1: xw_b = x @ W_b    (K=512, no split)
    dim3 g1(mtiles, 2, 1);
    gemm_tf32_kernel<<<g1, NTHREADS, SMEM_BYTES>>>(x, x, W1, W2, xw, MROWS, 512, 512);

    // GEMM2: partials of adj_b @ xw_b   (K=10000 split 5-ways)
    dim3 g2(mtiles, 2, KSPL);
    gemm_tf32_kernel<<<g2, NTHREADS, SMEM_BYTES>>>(adj1, adj2, xw, xw + MROWS * HID, part,
                                                   MROWS, MROWS, MROWS / KSPL);

    // Fuse: reduce partials + bias, attention softmax, emb, q
    float* out = (float*)d_out;
    float* emb_out;
    float* q_out;
    const int embN = MROWS * HID;        // 640000
    const int qN   = MROWS * 10;         // 100000
    if (out_size >= embN + qN)      { emb_out = out;  q_out = out + embN; }
    else if (out_size >= embN)      { emb_out = out;  q_out = nullptr;    }
    else                            { emb_out = embS; q_out = out;        }

    fuse_kernel<<<(MROWS + 7) / 8, 256>>>(part, b1, b2, attn, clus, emb_out, q_out, MROWS);
}

// round 10
// speedup vs baseline: 1.1049x; 1.1049x over previous
#include <cuda_runtime.h>
#include <cstdint>
#include <math.h>

// Problem constants
#define MROWS 10000
#define NFEAT 512
#define HID   64
#define KSPL  5          // K-split for the big GEMM (10000/5 = 2000 = 125 * BK)

// GEMM tiling: CTA tile 128x64, 8 warps (4m x 2n), warp tile 32x32
#define BM 128
#define BN 64
#define BK 16
#define KPAD 20          // A smem row stride (floats): conflict-free a-frag reads
#define NPAD 72          // B smem row stride (floats): conflict-free b-frag reads

#define STAGES 4
#define WAIT_N 2         // STAGES-2: oldest outstanding group complete
#define AS_SZ (BM * KPAD)        // 2560 floats
#define BS_SZ (BK * NPAD)        // 1152 floats
#define STAGE_FLTS (AS_SZ + BS_SZ)               // 3712
#define SMEM_BYTES (STAGES * STAGE_FLTS * 4)     // 59392 (x3 CTAs = 178KB/SM)

// Scratch (static device globals: no allocation anywhere)
__device__ __align__(16) float g_xw[2 * MROWS * HID];          // x@W1, x@W2 (tf32-rounded)
__device__ __align__(16) float g_wr[2 * NFEAT * HID];          // W1, W2 rounded to tf32
__device__ __align__(16) float g_part[2 * KSPL * MROWS * HID]; // K-split partials
__device__ __align__(16) float g_emb[MROWS * HID];             // fallback emb target

__device__ __forceinline__ uint32_t f2tf(float x) {
    uint32_t u;
    asm("cvt.rna.tf32.f32 %0, %1;" : "=r"(u) : "f"(x));
    return u;
}

__device__ __forceinline__ void cp16(uint32_t dst, const void* src, bool v) {
    const int sz = v ? 16 : 0;   // src-size 0 => zero-fill, no gmem access
    asm volatile("cp.async.cg.shared.global [%0], [%1], 16, %2;\n"
                 :: "r"(dst), "l"(src), "r"(sz));
}

__device__ __forceinline__ void cp_commit() {
    asm volatile("cp.async.commit_group;\n");
}

__device__ __forceinline__ void cp_wait() {
    asm volatile("cp.async.wait_group %0;\n" :: "n"(WAIT_N));
}

__device__ __forceinline__ void mma8(float& c0, float& c1, float& c2, float& c3,
                                     uint32_t a0, uint32_t a1, uint32_t a2, uint32_t a3,
                                     uint32_t b0, uint32_t b1) {
    asm("mma.sync.aligned.m16n8k8.row.col.f32.tf32.tf32.f32 "
        "{%0,%1,%2,%3}, {%4,%5,%6,%7}, {%8,%9}, {%0,%1,%2,%3};"
        : "+f"(c0), "+f"(c1), "+f"(c2), "+f"(c3)
        : "r"(a0), "r"(a1), "r"(a2), "r"(a3), "r"(b0), "r"(b1));
}

// Round W1, W2 to tf32 once (B operand of GEMM1).
__global__ void prep_w_kernel(const float* __restrict__ W1, const float* __restrict__ W2,
                              float* __restrict__ wr)
{
    const int i = blockIdx.x * blockDim.x + threadIdx.x;
    if (i < NFEAT * HID) {
        wr[i]               = __uint_as_float(f2tf(W1[i]));
        wr[NFEAT * HID + i] = __uint_as_float(f2tf(W2[i]));
    }
}

// C[(by*gridDim.z + bz)*M*64 + m*64 + n] = A_by[m, kBase:kBase+kChunk] @ B_by[kBase:..., :64]
// A row-major (row stride lda), B row-major [K,64]. kChunk % BK == 0 guaranteed.
// A fragments: +0x1000 bit-bias makes HW tf32 truncation equal RNA rounding.
// B must be pre-rounded to tf32 by the caller. 4-stage cp.async pipeline.
__global__ __launch_bounds__(256, 3)
void gemm_tf32_kernel(const float* __restrict__ A0, const float* __restrict__ A1,
                      const float* __restrict__ B0, const float* __restrict__ B1,
                      float* __restrict__ Cbase, int M, int lda, int kChunk, int roundC)
{
    extern __shared__ __align__(16) float dsmem[];

    const int tid  = threadIdx.x;
    const float* A = blockIdx.y ? A1 : A0;
    const float* B = blockIdx.y ? B1 : B0;
    float* C = Cbase + (size_t)(blockIdx.y * gridDim.z + blockIdx.z) * ((size_t)M * BN);

    const int m0     = blockIdx.x * BM;
    const int kBase  = blockIdx.z * kChunk;
    const int ktiles = kChunk / BK;

    const int lane = tid & 31;
    const int warp = tid >> 5;
    const int wm0  = (warp & 3) * 32;   // warp grid 4(m) x 2(n); warp tile 32x32
    const int wn0  = (warp >> 2) * 32;
    const int r    = lane >> 2;         // 0..7
    const int c    = lane & 3;          // 0..3

    // global->smem staging mapping (16B chunks)
    const int arow = tid >> 2;          // 0..63 (and +64)
    const int acol = (tid & 3) * 4;     // 0,4,8,12
    const int brow = tid >> 4;          // 0..15
    const int bcol = (tid & 15) * 4;    // 0..60

    const int  ar0 = m0 + arow;
    const int  ar1 = ar0 + 64;
    const bool v0  = ar0 < M;
    const bool v1  = ar1 < M;

    // global src pointers (clamped rows when invalid; src-size=0 prevents access)
    const float* gA0 = A + (size_t)(v0 ? ar0 : 0) * lda + kBase + acol;
    const float* gA1 = A + (size_t)(v1 ? ar1 : 0) * lda + kBase + acol;
    const float* gB  = B + (size_t)(kBase + brow) * BN + bcol;

    // smem dst (per-thread, per-stage)
    const uint32_t sBase = (uint32_t)__cvta_generic_to_shared(dsmem);
    const uint32_t dA0   = sBase + (arow * KPAD + acol) * 4;
    const uint32_t dA1   = sBase + ((arow + 64) * KPAD + acol) * 4;
    const uint32_t dB    = sBase + (AS_SZ + brow * NPAD + bcol) * 4;
    const uint32_t stgB  = STAGE_FLTS * 4;

    float acc[2][4][4];
#pragma unroll
    for (int a = 0; a < 2; ++a)
#pragma unroll
        for (int b = 0; b < 4; ++b)
#pragma unroll
            for (int d = 0; d < 4; ++d) acc[a][b][d] = 0.f;

    // prologue: fill STAGES-1 stages
#pragma unroll
    for (int s = 0; s < STAGES - 1; ++s) {
        if (s < ktiles) {
            const uint32_t so = s * stgB;
            cp16(dA0 + so, gA0 + s * BK, v0);
            cp16(dA1 + so, gA1 + s * BK, v1);
            cp16(dB + so,  gB + (size_t)s * BK * BN, true);
        }
        cp_commit();
    }

    int rd = 0;                 // stage holding tile t
    int wr = STAGES - 1;        // stage for tile t+STAGES-1

    const uint32_t* dsmemU = (const uint32_t*)dsmem;

    for (int t = 0; t < ktiles; ++t) {
        cp_wait();              // tile t resident
        __syncthreads();        // all threads past iteration t-1's compute

        {   // issue loads for tile t+STAGES-1 into stage wr
            const int tt = t + STAGES - 1;
            if (tt < ktiles) {
                const uint32_t so = wr * stgB;
                cp16(dA0 + so, gA0 + tt * BK, v0);
                cp16(dA1 + so, gA1 + tt * BK, v1);
                cp16(dB + so,  gB + (size_t)tt * BK * BN, true);
            }
            cp_commit();
            if (++wr == STAGES) wr = 0;
        }

        const uint32_t* Ab = dsmemU + rd * STAGE_FLTS;
        const uint32_t* Bb = Ab + AS_SZ;
        if (++rd == STAGES) rd = 0;

#pragma unroll
        for (int ks = 0; ks < 2; ++ks) {
            const int k8 = ks * 8;
            uint32_t af[2][4], bf[4][2];
#pragma unroll
            for (int mt = 0; mt < 2; ++mt) {
                const int row = wm0 + mt * 16 + r;
                // +0x1000: HW truncation of biased bits == RNA tf32 rounding
                af[mt][0] = Ab[row       * KPAD + k8 + c]     + 0x1000u;
                af[mt][1] = Ab[(row + 8) * KPAD + k8 + c]     + 0x1000u;
                af[mt][2] = Ab[row       * KPAD + k8 + c + 4] + 0x1000u;
                af[mt][3] = Ab[(row + 8) * KPAD + k8 + c + 4] + 0x1000u;
            }
#pragma unroll
            for (int nt = 0; nt < 4; ++nt) {
                const int col = wn0 + nt * 8 + r;
                bf[nt][0] = Bb[(k8 + c)     * NPAD + col];
                bf[nt][1] = Bb[(k8 + c + 4) * NPAD + col];
            }
#pragma unroll
            for (int mt = 0; mt < 2; ++mt)
#pragma unroll
                for (int nt = 0; nt < 4; ++nt)
                    mma8(acc[mt][nt][0], acc[mt][nt][1], acc[mt][nt][2], acc[mt][nt][3],
                         af[mt][0], af[mt][1], af[mt][2], af[mt][3],
                         bf[nt][0], bf[nt][1]);
        }
    }

    // epilogue; optionally round to tf32 (GEMM1 -> clean B operand for GEMM2)
    if (roundC) {
#pragma unroll
        for (int a = 0; a < 2; ++a)
#pragma unroll
            for (int b = 0; b < 4; ++b)
#pragma unroll
                for (int d = 0; d < 4; ++d)
                    acc[a][b][d] = __uint_as_float(f2tf(acc[a][b][d]));
    }

#pragma unroll
    for (int mt = 0; mt < 2; ++mt) {
        const int rowA = m0 + wm0 + mt * 16 + r;
        const int rowB = rowA + 8;
#pragma unroll
        for (int nt = 0; nt < 4; ++nt) {
            const int col = wn0 + nt * 8 + 2 * c;
            if (rowA < M)
                *(float2*)(C + (size_t)rowA * BN + col) =
                    make_float2(acc[mt][nt][0], acc[mt][nt][1]);
            if (rowB < M)
                *(float2*)(C + (size_t)rowB * BN + col) =
                    make_float2(acc[mt][nt][2], acc[mt][nt][3]);
        }
    }
}

// One warp per node row: reduce K-split partials + bias, 2-view attention
// softmax fuse, DEC soft assignment q.
__global__ void fuse_kernel(const float* __restrict__ part,
                            const float* __restrict__ b1, const float* __restrict__ b2,
                            const float* __restrict__ attnw, const float* __restrict__ clus,
                            float* __restrict__ emb_out, float* __restrict__ q_out, int M)
{
    const int warp = threadIdx.x >> 5;
    const int lane = threadIdx.x & 31;
    const int i = blockIdx.x * 8 + warp;
    if (i >= M) return;

    const int h0 = lane, h1 = lane + 32;
    const size_t M64 = (size_t)M * HID;

    float e1a = b1[h0], e1b = b1[h1];
    float e2a = b2[h0], e2b = b2[h1];
    const float* p1 = part + (size_t)i * HID;
    const float* p2 = part + (size_t)KSPL * M64 + (size_t)i * HID;
#pragma unroll
    for (int z = 0; z < KSPL; ++z) {
        e1a += p1[(size_t)z * M64 + h0];
        e1b += p1[(size_t)z * M64 + h1];
        e2a += p2[(size_t)z * M64 + h0];
        e2b += p2[(size_t)z * M64 + h1];
    }

    const float aw0 = attnw[h0], aw1 = attnw[h1];
    float w1 = e1a * aw0 + e1b * aw1;
    float w2 = e2a * aw0 + e2b * aw1;
#pragma unroll
    for (int o = 16; o; o >>= 1) {
        w1 += __shfl_xor_sync(0xffffffffu, w1, o);
        w2 += __shfl_xor_sync(0xffffffffu, w2, o);
    }
    const float mx  = fmaxf(w1, w2);
    const float x1  = expf(w1 - mx);
    const float x2  = expf(w2 - mx);
    const float inv = 1.f / (x1 + x2);
    const float be1 = x1 * inv, be2 = x2 * inv;

    const float ea = be1 * e1a + be2 * e2a;
    const float eb = be1 * e1b + be2 * e2b;
    emb_out[(size_t)i * HID + h0] = ea;
    emb_out[(size_t)i * HID + h1] = eb;

    if (!q_out) return;

    float tq[10];
    float s = 0.f;
#pragma unroll
    for (int k = 0; k < 10; ++k) {
        const float da = ea - clus[k * HID + h0];
        const float db = eb - clus[k * HID + h1];
        float d2 = da * da + db * db;
#pragma unroll
        for (int o = 16; o; o >>= 1) d2 += __shfl_xor_sync(0xffffffffu, d2, o);
        // q = (1/(1+d2/0.2))^0.6 ^1.2 (/2 cancels under row normalization)
        float tk = 1.f / (1.f + d2 * 5.0f);
        tk = powf(tk, 0.72f);
        tq[k] = tk;
        s += tk;
    }
    if (lane < 10) q_out[(size_t)i * 10 + lane] = tq[lane] / s;
}

extern "C" void kernel_launch(void* const* d_in, const int* in_sizes, int n_in,
                              void* d_out, int out_size)
{
    const float* x    = (const float*)d_in[0];
    const float* adj1 = (const float*)d_in[1];
    const float* adj2 = (const float*)d_in[2];
    const float* W1   = (const float*)d_in[3];
    const float* b1   = (const float*)d_in[4];
    const float* W2   = (const float*)d_in[5];
    const float* b2   = (const float*)d_in[6];
    const float* attn = (const float*)d_in[7];
    const float* clus = (const float*)d_in[8];

    float *xw, *wr, *part, *embS;
    cudaGetSymbolAddress((void**)&xw,   g_xw);
    cudaGetSymbolAddress((void**)&wr,   g_wr);
    cudaGetSymbolAddress((void**)&part, g_part);
    cudaGetSymbolAddress((void**)&embS, g_emb);

    cudaFuncSetAttribute(gemm_tf32_kernel,
                         cudaFuncAttributeMaxDynamicSharedMemorySize, SMEM_BYTES);

    const int mtiles = (MROWS + BM - 1) / BM;   // 79

    // Prep: round W1, W2 to tf32 (B operand of GEMM1 must be pre-rounded)
    prep_w_kernel<<<(NFEAT * HID + 255) / 256, 256>>>(W1, W2, wr);

    // GEMM1: xw_b = x @ W_b    (K=512, no split); output pre-rounded to tf32
    dim3 g1(mtiles, 2, 1);
    gemm_tf32_kernel<<<g1, 256, SMEM_BYTES>>>(x, x, wr, wr + NFEAT * HID, xw,
                                              MROWS, 512, 512, 1);

    // GEMM2: partials of adj_b @ xw_b   (K=10000 split 5-ways); full-precision output
    dim3 g2(mtiles, 2, KSPL);
    gemm_tf32_kernel<<<g2, 256, SMEM_BYTES>>>(adj1, adj2, xw, xw + MROWS * HID, part,
                                              MROWS, MROWS, MROWS / KSPL, 0);

    // Fuse: reduce partials + bias, attention softmax, emb, q
    float* out = (float*)d_out;
    float* emb_out;
    float* q_out;
    const int embN = MROWS * HID;        // 640000
    const int qN   = MROWS * 10;         // 100000
    if (out_size >= embN + qN)      { emb_out = out;  q_out = out + embN; }
    else if (out_size >= embN)      { emb_out = out;  q_out = nullptr;    }
    else                            { emb_out = embS; q_out = out;        }

    fuse_kernel<<<(MROWS + 7) / 8, 256>>>(part, b1, b2, attn, clus, emb_out, q_out, MROWS);
}

// round 12
// speedup vs baseline: 1.1833x; 1.0710x over previous
#include <cuda_runtime.h>
#include <cstdint>
#include <math.h>

// Problem constants
#define MROWS 10000
#define NFEAT 512
#define HID   64
#define MTILES 79               // ceil(10000/128) per branch
#define SEGS  (2 * MTILES)      // 158 (branch-major segments)
#define NC    444               // persistent CTAs = 148 SMs x 3
#define PSLOTS 4                // max partial pieces per segment (range>=KT/4 guaranteed)

// GEMM tiling: CTA tile 128x64, 8 warps (4m x 2n), warp tile 32x32
#define BM 128
#define BN 64
#define BK 16
#define KPAD 20          // A smem row stride (floats): conflict-free a-frag reads
#define NPAD 72          // B smem row stride (floats): conflict-free b-frag reads

#define STAGES 4
#define WAIT_N 2         // STAGES-2: oldest outstanding group complete
#define AS_SZ (BM * KPAD)        // 2560 floats
#define BS_SZ (BK * NPAD)        // 1152 floats
#define STAGE_FLTS (AS_SZ + BS_SZ)               // 3712
#define SMEM_BYTES (STAGES * STAGE_FLTS * 4)     // 59392 (x3 CTAs = 178KB/SM)

// GEMM1: x@W, K=512 -> 32 k-tiles/segment.  GEMM2: adj@xw, K=10000 -> 625 k-tiles.
#define KT1 32
#define TOT1 ((long long)SEGS * KT1)    // 5056
#define KT2 625
#define TOT2 ((long long)SEGS * KT2)    // 98750

// Scratch (static device globals: no allocation anywhere)
__device__ __align__(16) float g_xw[2 * MROWS * HID];            // x@W1, x@W2 (tf32-rounded)
__device__ __align__(16) float g_wr[2 * NFEAT * HID];            // W1, W2 rounded to tf32
__device__ __align__(16) float g_part[SEGS * PSLOTS * BM * HID]; // piece partials (20.7MB)
__device__ __align__(16) float g_emb[MROWS * HID];               // fallback emb target

__device__ __forceinline__ uint32_t f2tf(float x) {
    uint32_t u;
    asm("cvt.rna.tf32.f32 %0, %1;" : "=r"(u) : "f"(x));
    return u;
}

// CTA index owning flattened tile T (ranges: start(g) = floor(g*TOTAL/NC))
__device__ __forceinline__ int g_of(long long T, long long TOTAL) {
    return (int)(((T + 1) * NC - 1) / TOTAL);
}

__device__ __forceinline__ void cp16(uint32_t dst, const void* src, bool v) {
    const int sz = v ? 16 : 0;   // src-size 0 => zero-fill, no gmem access
    asm volatile("cp.async.cg.shared.global [%0], [%1], 16, %2;\n"
                 :: "r"(dst), "l"(src), "r"(sz));
}
__device__ __forceinline__ void cp_commit() { asm volatile("cp.async.commit_group;\n"); }
__device__ __forceinline__ void cp_wait()   { asm volatile("cp.async.wait_group %0;\n" :: "n"(WAIT_N)); }

__device__ __forceinline__ void mma8(float& c0, float& c1, float& c2, float& c3,
                                     uint32_t a0, uint32_t a1, uint32_t a2, uint32_t a3,
                                     uint32_t b0, uint32_t b1) {
    asm("mma.sync.aligned.m16n8k8.row.col.f32.tf32.tf32.f32 "
        "{%0,%1,%2,%3}, {%4,%5,%6,%7}, {%8,%9}, {%0,%1,%2,%3};"
        : "+f"(c0), "+f"(c1), "+f"(c2), "+f"(c3)
        : "r"(a0), "r"(a1), "r"(a2), "r"(a3), "r"(b0), "r"(b1));
}

// Round W1, W2 to tf32 once (B operand of GEMM1).
__global__ void prep_w_kernel(const float* __restrict__ W1, const float* __restrict__ W2,
                              float* __restrict__ wr)
{
    const int i = blockIdx.x * blockDim.x + threadIdx.x;
    if (i < NFEAT * HID) {
        wr[i]               = __uint_as_float(f2tf(W1[i]));
        wr[NFEAT * HID + i] = __uint_as_float(f2tf(W2[i]));
    }
}

// Persistent GEMM: NC CTAs statically split the flattened tile sequence
// (segment s = branch*79 + mtile, each KT k-tiles) into equal contiguous
// ranges. Per segment-piece, acc is flushed to part[(s*PSLOTS+p)], where
// p = g - g_of(first tile of s). A fragments get +0x1000 (truncation->RNA);
// B must be pre-rounded to tf32.
__global__ __launch_bounds__(256, 3)
void gemm_persist(const float* __restrict__ A0, const float* __restrict__ A1,
                  const float* __restrict__ B0, const float* __restrict__ B1,
                  float* __restrict__ part, int M, int lda, int KT, long long TOTAL)
{
    extern __shared__ __align__(16) float dsmem[];

    const int g = blockIdx.x;
    const long long rngS = ((long long)g * TOTAL) / NC;
    const long long rngE = ((long long)(g + 1) * TOTAL) / NC;

    const int tid  = threadIdx.x;
    const int lane = tid & 31;
    const int warp = tid >> 5;
    const int wm0  = (warp & 3) * 32;
    const int wn0  = (warp >> 2) * 32;
    const int r    = lane >> 2;
    const int c    = lane & 3;

    const int arow = tid >> 2;          // 0..63 (and +64)
    const int acol = (tid & 3) * 4;
    const int brow = tid >> 4;          // 0..15
    const int bcol = (tid & 15) * 4;

    const uint32_t sBase = (uint32_t)__cvta_generic_to_shared(dsmem);
    const uint32_t dA0   = sBase + (arow * KPAD + acol) * 4;
    const uint32_t dA1   = sBase + ((arow + 64) * KPAD + acol) * 4;
    const uint32_t dB    = sBase + (AS_SZ + brow * NPAD + bcol) * 4;
    const uint32_t stgB  = STAGE_FLTS * 4;
    const uint32_t* dsmemU = (const uint32_t*)dsmem;

    long long cur = rngS;
    while (cur < rngE) {
        const int s   = (int)(cur / KT);
        const int k0  = (int)(cur % KT);
        const int kc  = (int)min((long long)(KT - k0), rngE - cur);   // tiles this chunk
        const int p   = g - g_of((long long)s * KT, TOTAL);
        const int br  = s / MTILES;
        const int mt  = s % MTILES;
        const int m0  = mt * BM;
        const int kBase = k0 * BK;

        const float* A = br ? A1 : A0;
        const float* B = br ? B1 : B0;

        const int  ar0 = m0 + arow;
        const int  ar1 = ar0 + 64;
        const bool v0  = ar0 < M;
        const bool v1  = ar1 < M;
        const float* gA0 = A + (size_t)(v0 ? ar0 : 0) * lda + kBase + acol;
        const float* gA1 = A + (size_t)(v1 ? ar1 : 0) * lda + kBase + acol;
        const float* gB  = B + (size_t)(kBase + brow) * BN + bcol;

        float acc[2][4][4];
#pragma unroll
        for (int a = 0; a < 2; ++a)
#pragma unroll
            for (int b = 0; b < 4; ++b)
#pragma unroll
                for (int d = 0; d < 4; ++d) acc[a][b][d] = 0.f;

        __syncthreads();        // all warps done reading smem from previous chunk

        // prologue: fill STAGES-1 stages
#pragma unroll
        for (int st = 0; st < STAGES - 1; ++st) {
            if (st < kc) {
                const uint32_t so = st * stgB;
                cp16(dA0 + so, gA0 + st * BK, v0);
                cp16(dA1 + so, gA1 + st * BK, v1);
                cp16(dB + so,  gB + (size_t)st * BK * BN, true);
            }
            cp_commit();
        }

        int rd = 0, wr = STAGES - 1;

        for (int t = 0; t < kc; ++t) {
            cp_wait();
            __syncthreads();

            {   // prefetch tile t+STAGES-1
                const int tt = t + STAGES - 1;
                if (tt < kc) {
                    const uint32_t so = wr * stgB;
                    cp16(dA0 + so, gA0 + tt * BK, v0);
                    cp16(dA1 + so, gA1 + tt * BK, v1);
                    cp16(dB + so,  gB + (size_t)tt * BK * BN, true);
                }
                cp_commit();
                if (++wr == STAGES) wr = 0;
            }

            const uint32_t* Ab = dsmemU + rd * STAGE_FLTS;
            const uint32_t* Bb = Ab + AS_SZ;
            if (++rd == STAGES) rd = 0;

#pragma unroll
            for (int ks = 0; ks < 2; ++ks) {
                const int k8 = ks * 8;
                uint32_t af[2][4], bf[4][2];
#pragma unroll
                for (int mt_ = 0; mt_ < 2; ++mt_) {
                    const int row = wm0 + mt_ * 16 + r;
                    af[mt_][0] = Ab[row       * KPAD + k8 + c]     + 0x1000u;
                    af[mt_][1] = Ab[(row + 8) * KPAD + k8 + c]     + 0x1000u;
                    af[mt_][2] = Ab[row       * KPAD + k8 + c + 4] + 0x1000u;
                    af[mt_][3] = Ab[(row + 8) * KPAD + k8 + c + 4] + 0x1000u;
                }
#pragma unroll
                for (int nt = 0; nt < 4; ++nt) {
                    const int col = wn0 + nt * 8 + r;
                    bf[nt][0] = Bb[(k8 + c)     * NPAD + col];
                    bf[nt][1] = Bb[(k8 + c + 4) * NPAD + col];
                }
#pragma unroll
                for (int mt_ = 0; mt_ < 2; ++mt_)
#pragma unroll
                    for (int nt = 0; nt < 4; ++nt)
                        mma8(acc[mt_][nt][0], acc[mt_][nt][1], acc[mt_][nt][2], acc[mt_][nt][3],
                             af[mt_][0], af[mt_][1], af[mt_][2], af[mt_][3],
                             bf[nt][0], bf[nt][1]);
            }
        }

        // flush piece: part[(s*PSLOTS+p)][localRow][col], rows unguarded (OOB rows are 0)
        float* dst = part + ((size_t)(s * PSLOTS + p) * BM) * HID;
#pragma unroll
        for (int mt_ = 0; mt_ < 2; ++mt_) {
            const int rowA = wm0 + mt_ * 16 + r;
            const int rowB = rowA + 8;
#pragma unroll
            for (int nt = 0; nt < 4; ++nt) {
                const int col = wn0 + nt * 8 + 2 * c;
                *(float2*)(dst + (size_t)rowA * HID + col) =
                    make_float2(acc[mt_][nt][0], acc[mt_][nt][1]);
                *(float2*)(dst + (size_t)rowB * HID + col) =
                    make_float2(acc[mt_][nt][2], acc[mt_][nt][3]);
            }
        }

        cur += kc;
    }
}

// Reduce GEMM1 pieces -> xw (tf32-rounded). One warp per (branch,row).
__global__ void reduce_xw_kernel(const float* __restrict__ part, float* __restrict__ xw)
{
    const int warp = threadIdx.x >> 5;
    const int lane = threadIdx.x & 31;
    const int gi = blockIdx.x * 8 + warp;          // 0..19999 = b*MROWS + i
    if (gi >= 2 * MROWS) return;
    const int b = gi / MROWS;
    const int i = gi - b * MROWS;

    const int s = b * MTILES + (i >> 7);
    const long long t0 = (long long)s * KT1;
    const int np = g_of(t0 + KT1 - 1, TOT1) - g_of(t0, TOT1) + 1;

    const float* base = part + ((size_t)(s * PSLOTS) * BM + (i & 127)) * HID;
    float sa = 0.f, sb = 0.f;
#pragma unroll 4
    for (int p = 0; p < np; ++p) {
        sa += base[(size_t)p * BM * HID + lane];
        sb += base[(size_t)p * BM * HID + lane + 32];
    }
    float* o = xw + (size_t)b * MROWS * HID + (size_t)i * HID;
    o[lane]      = __uint_as_float(f2tf(sa));
    o[lane + 32] = __uint_as_float(f2tf(sb));
}

// One warp per node row: sum GEMM2 pieces + bias, 2-view attention softmax
// fuse, DEC soft assignment q.
__global__ void fuse_kernel(const float* __restrict__ part,
                            const float* __restrict__ b1, const float* __restrict__ b2,
                            const float* __restrict__ attnw, const float* __restrict__ clus,
                            float* __restrict__ emb_out, float* __restrict__ q_out, int M)
{
    const int warp = threadIdx.x >> 5;
    const int lane = threadIdx.x & 31;
    const int i = blockIdx.x * 8 + warp;
    if (i >= M) return;

    const int h0 = lane, h1 = lane + 32;
    const int rloc = i & 127;
    const int mt   = i >> 7;

    float e1a = b1[h0], e1b = b1[h1];
    float e2a = b2[h0], e2b = b2[h1];

    {   // branch 1: segment mt
        const int s = mt;
        const long long t0 = (long long)s * KT2;
        const int np = g_of(t0 + KT2 - 1, TOT2) - g_of(t0, TOT2) + 1;
        const float* base = part + ((size_t)(s * PSLOTS) * BM + rloc) * HID;
#pragma unroll 4
        for (int p = 0; p < np; ++p) {
            e1a += base[(size_t)p * BM * HID + h0];
            e1b += base[(size_t)p * BM * HID + h1];
        }
    }
    {   // branch 2: segment 79+mt
        const int s = MTILES + mt;
        const long long t0 = (long long)s * KT2;
        const int np = g_of(t0 + KT2 - 1, TOT2) - g_of(t0, TOT2) + 1;
        const float* base = part + ((size_t)(s * PSLOTS) * BM + rloc) * HID;
#pragma unroll 4
        for (int p = 0; p < np; ++p) {
            e2a += base[(size_t)p * BM * HID + h0];
            e2b += base[(size_t)p * BM * HID + h1];
        }
    }

    const float aw0 = attnw[h0], aw1 = attnw[h1];
    float w1 = e1a * aw0 + e1b * aw1;
    float w2 = e2a * aw0 + e2b * aw1;
#pragma unroll
    for (int o = 16; o; o >>= 1) {
        w1 += __shfl_xor_sync(0xffffffffu, w1, o);
        w2 += __shfl_xor_sync(0xffffffffu, w2, o);
    }
    const float mx  = fmaxf(w1, w2);
    const float x1  = expf(w1 - mx);
    const float x2  = expf(w2 - mx);
    const float inv = 1.f / (x1 + x2);
    const float be1 = x1 * inv, be2 = x2 * inv;

    const float ea = be1 * e1a + be2 * e2a;
    const float eb = be1 * e1b + be2 * e2b;
    emb_out[(size_t)i * HID + h0] = ea;
    emb_out[(size_t)i * HID + h1] = eb;

    if (!q_out) return;

    float tq[10];
    float s = 0.f;
#pragma unroll
    for (int k = 0; k < 10; ++k) {
        const float da = ea - clus[k * HID + h0];
        const float db = eb - clus[k * HID + h1];
        float d2 = da * da + db * db;
#pragma unroll
        for (int o = 16; o; o >>= 1) d2 += __shfl_xor_sync(0xffffffffu, d2, o);
        // q = (1/(1+d2/0.2))^0.72 (the /2 cancels under row normalization)
        float tk = 1.f / (1.f + d2 * 5.0f);
        tk = __powf(tk, 0.72f);
        tq[k] = tk;
        s += tk;
    }
    if (lane < 10) q_out[(size_t)i * 10 + lane] = tq[lane] / s;
}

extern "C" void kernel_launch(void* const* d_in, const int* in_sizes, int n_in,
                              void* d_out, int out_size)
{
    const float* x    = (const float*)d_in[0];
    const float* adj1 = (const float*)d_in[1];
    const float* adj2 = (const float*)d_in[2];
    const float* W1   = (const float*)d_in[3];
    const float* b1   = (const float*)d_in[4];
    const float* W2   = (const float*)d_in[5];
    const float* b2   = (const float*)d_in[6];
    const float* attn = (const float*)d_in[7];
    const float* clus = (const float*)d_in[8];

    float *xw, *wr, *part, *embS;
    cudaGetSymbolAddress((void**)&xw,   g_xw);
    cudaGetSymbolAddress((void**)&wr,   g_wr);
    cudaGetSymbolAddress((void**)&part, g_part);
    cudaGetSymbolAddress((void**)&embS, g_emb);

    cudaFuncSetAttribute(gemm_persist,
                         cudaFuncAttributeMaxDynamicSharedMemorySize, SMEM_BYTES);

    // Prep: round W1, W2 to tf32 (B operand of GEMM1 must be pre-rounded)
    prep_w_kernel<<<(NFEAT * HID + 255) / 256, 256>>>(W1, W2, wr);

    // GEMM1: pieces of x @ W_b  (persistent, balanced)
    gemm_persist<<<NC, 256, SMEM_BYTES>>>(x, x, wr, wr + NFEAT * HID, part,
                                          MROWS, NFEAT, KT1, TOT1);

    // Reduce GEMM1 pieces -> xw (tf32-rounded)
    reduce_xw_kernel<<<(2 * MROWS + 7) / 8, 256>>>(part, xw);

    // GEMM2: pieces of adj_b @ xw_b  (persistent, balanced)
    gemm_persist<<<NC, 256, SMEM_BYTES>>>(adj1, adj2, xw, xw + MROWS * HID, part,
                                          MROWS, MROWS, KT2, TOT2);

    // Fuse: sum pieces + bias, attention softmax, emb, q
    float* out = (float*)d_out;
    float* emb_out;
    float* q_out;
    const int embN = MROWS * HID;        // 640000
    const int qN   = MROWS * 10;         // 100000
    if (out_size >= embN + qN)      { emb_out = out;  q_out = out + embN; }
    else if (out_size >= embN)      { emb_out = out;  q_out = nullptr;    }
    else                            { emb_out = embS; q_out = out;        }

    fuse_kernel<<<(MROWS + 7) / 8, 256>>>(part, b1, b2, attn, clus, emb_out, q_out, MROWS);
}